// round 3
// baseline (speedup 1.0000x reference)
#include <cuda_runtime.h>

// KANModel fused forward:
//   x = concat(emb_user[u], emb_item[v])            (1024 x 128)
//   L0: y[b,o] = sum_i sb0*silu(x) + ssp0*<coef0, B(x)>   (128 -> 64)
//   L1: same form (64 -> 1), then sigmoid.
// Key identity: spline basis depends only on (b, i), not o. So build a
// 9-wide feature (silu + 8 cubic B-spline bases) per (b,i) once, then the
// layer is a dense contraction.

namespace {
constexpr int GI    = 5;     // grid intervals
constexpr int NBAS  = 8;     // G + K basis functions
constexpr int TB    = 8;     // batch tile per block
constexpr int BLOCK = 256;
constexpr int DIN0  = 128;
constexpr int DOUT0 = 64;
constexpr int NC    = 9;     // silu + 8 bases
}

// Cox-de-Boor on 12 uniform-extended knots -> 8 cubic bases.
__device__ __forceinline__ void bspline8(float x, const float* t, float* out) {
    float B[11];
#pragma unroll
    for (int j = 0; j < 11; ++j)
        B[j] = (x >= t[j] && x < t[j + 1]) ? 1.0f : 0.0f;
#pragma unroll
    for (int kk = 1; kk <= 3; ++kk) {
#pragma unroll
        for (int j = 0; j < 11 - kk; ++j) {
            B[j] = (x - t[j]) / (t[j + kk] - t[j]) * B[j]
                 + (t[j + kk + 1] - x) / (t[j + kk + 1] - t[j + 1]) * B[j + 1];
        }
    }
#pragma unroll
    for (int j = 0; j < NBAS; ++j) out[j] = B[j];
}

__device__ __forceinline__ void make_knots(const float* __restrict__ g, float* t) {
    float h = (g[5] - g[0]) * (1.0f / GI);
    t[0] = g[0] - 3.f * h; t[1] = g[0] - 2.f * h; t[2] = g[0] - h;
#pragma unroll
    for (int j = 0; j < 6; ++j) t[3 + j] = g[j];
    t[9] = g[5] + h; t[10] = g[5] + 2.f * h; t[11] = g[5] + 3.f * h;
}

__device__ __forceinline__ float silu_f(float x) {
    return x * (1.0f / (1.0f + __expf(-x)));
}

__global__ __launch_bounds__(BLOCK) void kan_fused(
    const int*   __restrict__ uidx,  const int*   __restrict__ vidx,
    const float* __restrict__ emb_u, const float* __restrict__ emb_v,
    const float* __restrict__ grid0, const float* __restrict__ coef0,
    const float* __restrict__ sb0,   const float* __restrict__ ssp0,
    const float* __restrict__ bias0,
    const float* __restrict__ grid1, const float* __restrict__ coef1,
    const float* __restrict__ sb1,   const float* __restrict__ ssp1,
    const float* __restrict__ bias1,
    float* __restrict__ out)
{
    __shared__ float f[DIN0 * NC * TB];   // [i][c][b], b fastest
    __shared__ float z[TB][DOUT0];        // layer-0 activations
    const int tid = threadIdx.x;
    const int b0  = blockIdx.x * TB;

    // All grid rows are identical by construction -> knots from row 0.
    float t0[12];
    {
        float g[6];
#pragma unroll
        for (int j = 0; j < 6; ++j) g[j] = grid0[j];
        make_knots(g, t0);
    }

    // ---- Phase A: build features f[i,c,b] = (silu(x), B_0..B_7(x)) ----
#pragma unroll
    for (int k = 0; k < (TB * DIN0) / BLOCK; ++k) {
        int fi = tid + k * BLOCK;
        int b  = fi >> 7;            // /128
        int i  = fi & (DIN0 - 1);
        int gb = b0 + b;
        float x = (i < 64) ? emb_u[uidx[gb] * 64 + i]
                           : emb_v[vidx[gb] * 64 + (i - 64)];
        float Bv[NBAS];
        bspline8(x, t0, Bv);
        f[(i * NC + 0) * TB + b] = silu_f(x);
#pragma unroll
        for (int c = 0; c < NBAS; ++c)
            f[(i * NC + 1 + c) * TB + b] = Bv[c];
    }
    __syncthreads();

    // ---- Phase B: layer-0 contraction. thread = (o, batch-pair) ----
    // y = sb*silu + ssp*(coef . B): compute the 8-wide dot first, then one
    // FMA by ssp -- avoids pre-scaling 8 coefs per (o,i).
    {
        const int o  = tid >> 2;       // 0..63
        const int bp = tid & 3;        // batches {2bp, 2bp+1}
        float acc0 = 0.f, acc1 = 0.f;
        const float4* c4 = (const float4*)coef0;
#pragma unroll 4
        for (int i = 0; i < DIN0; ++i) {
            int n = o * DIN0 + i;
            float sb  = sb0[n];
            float sp  = ssp0[n];
            float4 ca = c4[2 * n + 0];
            float4 cb = c4[2 * n + 1];
            const float* fb = &f[i * NC * TB];
            // base term (c = 0)
            {
                float2 v = *(const float2*)&fb[2 * bp];
                acc0 = fmaf(sb, v.x, acc0);
                acc1 = fmaf(sb, v.y, acc1);
            }
            float d0 = 0.f, d1 = 0.f;
            float w[NBAS] = {ca.x, ca.y, ca.z, ca.w, cb.x, cb.y, cb.z, cb.w};
#pragma unroll
            for (int c = 0; c < NBAS; ++c) {
                // whole warp reads the same 32B slice -> conflict-free bcast
                float2 v = *(const float2*)&fb[(1 + c) * TB + 2 * bp];
                d0 = fmaf(w[c], v.x, d0);
                d1 = fmaf(w[c], v.y, d1);
            }
            acc0 = fmaf(sp, d0, acc0);
            acc1 = fmaf(sp, d1, acc1);
        }
        float bb = bias0[o];
        z[2 * bp + 0][o] = acc0 + bb;
        z[2 * bp + 1][o] = acc1 + bb;
    }
    __syncthreads();

    // ---- Phase C: layer 1 (64 -> 1) + sigmoid. warp w <-> batch w ----
    {
        const int w    = tid >> 5;
        const int lane = tid & 31;
        float t1[12];
        {
            float g[6];
#pragma unroll
            for (int j = 0; j < 6; ++j) g[j] = grid1[j];
            make_knots(g, t1);
        }
        float part = 0.f;
        const float4* c4 = (const float4*)coef1;
        for (int oo = lane; oo < DOUT0; oo += 32) {
            float xz = z[w][oo];
            float Bv[NBAS];
            bspline8(xz, t1, Bv);
            float4 ca = c4[2 * oo + 0];
            float4 cb = c4[2 * oo + 1];
            float sdot = ca.x * Bv[0] + ca.y * Bv[1] + ca.z * Bv[2] + ca.w * Bv[3]
                       + cb.x * Bv[4] + cb.y * Bv[5] + cb.z * Bv[6] + cb.w * Bv[7];
            part += sb1[oo] * silu_f(xz) + ssp1[oo] * sdot;
        }
#pragma unroll
        for (int off = 16; off > 0; off >>= 1)
            part += __shfl_down_sync(0xffffffffu, part, off);
        if (lane == 0)
            out[b0 + w] = 1.0f / (1.0f + __expf(-(part + bias1[0])));
    }
}

extern "C" void kernel_launch(void* const* d_in, const int* in_sizes, int n_in,
                              void* d_out, int out_size) {
    // Robust to whether the two python-int scalars (grid_update_num,
    // stop_grid_update_step) are materialized as device inputs.
    // Full layout (16 inputs): 0:uidx 1:vidx 2:gun 3:sgus 4:emb_u 5:emb_v
    //   6:grid0 7:coef0 8:sb0 9:ssp0 10:bias0 11:grid1 12:coef1 13:sb1
    //   14:ssp1 15:bias1
    const int s = (n_in >= 16) ? 2 : (n_in - 14);  // scalar count present
    const int*   uidx  = (const int*)  d_in[0];
    const int*   vidx  = (const int*)  d_in[1];
    const float* embu  = (const float*)d_in[2 + s];
    const float* embv  = (const float*)d_in[3 + s];
    const float* grid0 = (const float*)d_in[4 + s];
    const float* coef0 = (const float*)d_in[5 + s];
    const float* sb0   = (const float*)d_in[6 + s];
    const float* ssp0  = (const float*)d_in[7 + s];
    const float* bias0 = (const float*)d_in[8 + s];
    const float* grid1 = (const float*)d_in[9 + s];
    const float* coef1 = (const float*)d_in[10 + s];
    const float* sb1   = (const float*)d_in[11 + s];
    const float* ssp1  = (const float*)d_in[12 + s];
    const float* bias1 = (const float*)d_in[13 + s];
    float* outp = (float*)d_out;

    const int batch = in_sizes[0];      // 1024
    const int nblk  = batch / TB;       // 128 blocks
    kan_fused<<<nblk, BLOCK>>>(uidx, vidx, embu, embv,
                               grid0, coef0, sb0, ssp0, bias0,
                               grid1, coef1, sb1, ssp1, bias1, outp);
}